// round 13
// baseline (speedup 1.0000x reference)
#include <cuda_runtime.h>
#include <cstdint>

// Problem constants (match reference_code)
#define USER_NUM  1000000
#define EMBED_DIM 64
#define BATCH     16384

// FM scoring: out[e] = w[u] + w[i] + b + dot(V[u], V[i])
//   (0.5*sum((Vu+Vi)^2 - Vu^2 - Vi^2) == sum(Vu*Vi))
// INPUT is int32 on the wire (JAX x64-off downgrades int64->int32).
//
// R2-R12: this problem sits on the chip's random-line service wall
// (~1.45TB/s here), invariant across LDG/cp.async/TMA/gather4 and all
// occupancy/MLP/hint shapes; DRAM traffic is already at the logical
// minimum (~8.65MB). Final form: 16 lanes/elem, 32-bit addressing, and
// the linear terms (w[u], w[i], b) loaded by lanes 1/2/3 and folded into
// the shuffle reduction -- no serial scalar-load tail on lane 0.
__global__ void __launch_bounds__(256) fm_score_kernel(
    const int*   __restrict__ inp,   // [BATCH, 2] int32
    const float* __restrict__ w,     // [USER_NUM + ITEM_NUM]
    const float* __restrict__ bptr,  // [1]
    const float* __restrict__ V,     // [USER_NUM + ITEM_NUM, 64]
    float*       __restrict__ out)   // [BATCH]
{
    const unsigned gid  = blockIdx.x * blockDim.x + threadIdx.x;
    const unsigned elem = gid >> 4;      // 16 lanes per element (grid exact)
    const unsigned lane = gid & 15;

    // Both indices in one 64-bit broadcast load.
    const int2 idx = __ldg(reinterpret_cast<const int2*>(inp) + elem);
    const unsigned u = (unsigned)idx.x;                 // < 100000
    const unsigned i = (unsigned)idx.y + USER_NUM;      // < 1100000

    // 32-bit element offsets (max 1.1M*64 = 70.4M < 2^31).
    const float4* up = reinterpret_cast<const float4*>(V + u * (unsigned)EMBED_DIM);
    const float4* ip = reinterpret_cast<const float4*>(V + i * (unsigned)EMBED_DIM);

    // Two 128-bit gathers back-to-back (rows are 256B-aligned).
    const float4 a = __ldg(up + lane);
    const float4 c = __ldg(ip + lane);

    // Linear terms: one scalar load each on lanes 1/2/3, issued in the
    // same cycle as each other and overlapped with the gathers. Folded
    // into the per-lane partial so the shuffle reduce sums them for free.
    float extra = 0.0f;
    if (lane == 1)      extra = __ldg(&w[u]);
    else if (lane == 2) extra = __ldg(&w[i]);
    else if (lane == 3) extra = __ldg(&bptr[0]);

    float part = extra + a.x * c.x + a.y * c.y + a.z * c.z + a.w * c.w;

    // Reduce across the 16-lane group (contiguous within the warp).
    #pragma unroll
    for (int off = 8; off > 0; off >>= 1)
        part += __shfl_xor_sync(0xffffffffu, part, off);

    if (lane == 0)
        out[elem] = part;
}

extern "C" void kernel_launch(void* const* d_in, const int* in_sizes, int n_in,
                              void* d_out, int out_size)
{
    const int*   inp = (const int*)d_in[0];    // INPUT int32 [BATCH,2]
    const float* w   = (const float*)d_in[1];  // w
    const float* b   = (const float*)d_in[2];  // b
    const float* V   = (const float*)d_in[3];  // V
    float*       out = (float*)d_out;          // [BATCH,1] float32

    const int threads = 256;
    const int blocks  = (BATCH * 16) / threads;   // 1024, exact
    fm_score_kernel<<<blocks, threads>>>(inp, w, b, V, out);
}

// round 14
// speedup vs baseline: 1.0419x; 1.0419x over previous
#include <cuda_runtime.h>
#include <cstdint>

// Problem constants (match reference_code)
#define USER_NUM  1000000
#define EMBED_DIM 64
#define BATCH     16384

// FM scoring: out[e] = w[u] + w[i] + b + dot(V[u], V[i])
//   (0.5*sum((Vu+Vi)^2 - Vu^2 - Vi^2) == sum(Vu*Vi))
// INPUT is int32 on the wire (JAX x64-off downgrades int64->int32).
//
// Final form (R12, measured best: wall 6.624us, kernel 5.95us, 1454GB/s).
// R2-R13 established:
//  - the problem sits on the chip's random-128B-line service wall
//    (~1.45TB/s), invariant across LDG/cp.async/TMA-bulk/gather4 and all
//    occupancy/MLP/width/cache-hint shapes;
//  - DRAM traffic is at the logical minimum (~8.65MB);
//  - w/b loads must stay on lane 0 AFTER the gathers (R13 showed folding
//    them into other lanes puts them on the shuffle-reduce critical path);
//  - 32-bit addressing + early-issued linear terms gave the only real
//    kernel-level win (6.34 -> 5.95us).
__global__ void __launch_bounds__(256) fm_score_kernel(
    const int*   __restrict__ inp,   // [BATCH, 2] int32
    const float* __restrict__ w,     // [USER_NUM + ITEM_NUM]
    const float* __restrict__ bptr,  // [1]
    const float* __restrict__ V,     // [USER_NUM + ITEM_NUM, 64]
    float*       __restrict__ out)   // [BATCH]
{
    const int gid  = blockIdx.x * blockDim.x + threadIdx.x;
    const int elem = gid >> 4;       // 16 lanes per element (grid is exact)
    const int lane = gid & 15;

    // Both indices in one 64-bit broadcast load.
    const int2 idx = __ldg(reinterpret_cast<const int2*>(inp) + elem);
    const unsigned u = (unsigned)idx.x;                 // < 100000
    const unsigned i = (unsigned)idx.y + USER_NUM;      // < 1100000

    // 32-bit element offsets (max 1.1M*64 = 70.4M < 2^31).
    const float* up = V + u * (unsigned)EMBED_DIM;
    const float* ip = V + i * (unsigned)EMBED_DIM;

    // Two 128-bit gathers back-to-back (rows are 256B-aligned).
    const float4 a = __ldg(reinterpret_cast<const float4*>(up) + lane);
    const float4 c = __ldg(reinterpret_cast<const float4*>(ip) + lane);

    // Linear terms issued early on lane 0, overlapped with the gathers and
    // the reduction (independent chain, consumed only at the final store).
    float wsum = 0.0f;
    if (lane == 0)
        wsum = __ldg(&w[u]) + __ldg(&w[i]) + __ldg(&bptr[0]);

    float dot = a.x * c.x + a.y * c.y + a.z * c.z + a.w * c.w;

    // Reduce across the 16-lane group (contiguous within the warp).
    #pragma unroll
    for (int off = 8; off > 0; off >>= 1)
        dot += __shfl_xor_sync(0xffffffffu, dot, off);

    if (lane == 0)
        out[elem] = wsum + dot;
}

extern "C" void kernel_launch(void* const* d_in, const int* in_sizes, int n_in,
                              void* d_out, int out_size)
{
    const int*   inp = (const int*)d_in[0];    // INPUT int32 [BATCH,2]
    const float* w   = (const float*)d_in[1];  // w
    const float* b   = (const float*)d_in[2];  // b
    const float* V   = (const float*)d_in[3];  // V
    float*       out = (float*)d_out;          // [BATCH,1] float32

    const int threads = 256;
    const int blocks  = (BATCH * 16) / threads;   // 1024, exact
    fm_score_kernel<<<blocks, threads>>>(inp, w, b, V, out);
}

// round 15
// speedup vs baseline: 1.0769x; 1.0337x over previous
#include <cuda_runtime.h>
#include <cstdint>

// Problem constants (match reference_code)
#define USER_NUM  1000000
#define EMBED_DIM 64
#define BATCH     16384

// FM scoring: out[e] = w[u] + w[i] + b + dot(V[u], V[i])
//   (0.5*sum((Vu+Vi)^2 - Vu^2 - Vi^2) == sum(Vu*Vi))
// INPUT is int32 on the wire (JAX x64-off downgrades int64->int32).
//
// FINAL FORM (R12 structure; measured best wall 6.624us, kernel 5.95us,
// 1454GB/s; R14 re-run of identical source: 6.88/6.14 -> +-3-4% run noise).
//
// Evidence base (R2-R14):
//  - The problem is pinned at the chip's random-128B-line service wall
//    (~1.4TB/s), invariant across LDG / cp.async / TMA-bulk / TMA-gather4,
//    all occupancies, per-thread MLP, load widths, prefetch & evict hints,
//    and dual-engine splits. DRAM traffic equals the logical minimum
//    (~8.65MB = 16384 x (512B V rows + w sectors + idx/out)).
//  - w/b loads live on lane 0, issued between the gathers and the reduce:
//    an independent chain overlapped with the reduction (R13 proved folding
//    them into other lanes puts them on the shuffle critical path: -8%).
//  - 32-bit addressing removed IMAD.WIDE chains (only real kernel win).
__global__ void __launch_bounds__(256) fm_score_kernel(
    const int*   __restrict__ inp,   // [BATCH, 2] int32
    const float* __restrict__ w,     // [USER_NUM + ITEM_NUM]
    const float* __restrict__ bptr,  // [1]
    const float* __restrict__ V,     // [USER_NUM + ITEM_NUM, 64]
    float*       __restrict__ out)   // [BATCH]
{
    const int gid  = blockIdx.x * blockDim.x + threadIdx.x;
    const int elem = gid >> 4;       // 16 lanes per element (grid is exact)
    const int lane = gid & 15;

    // Both indices in one 64-bit broadcast load.
    const int2 idx = __ldg(reinterpret_cast<const int2*>(inp) + elem);
    const unsigned u = (unsigned)idx.x;                 // < 100000
    const unsigned i = (unsigned)idx.y + USER_NUM;      // < 1100000

    // 32-bit element offsets (max 1.1M*64 = 70.4M < 2^31).
    const float* up = V + u * (unsigned)EMBED_DIM;
    const float* ip = V + i * (unsigned)EMBED_DIM;

    // Two 128-bit gathers back-to-back (rows are 256B-aligned).
    const float4 a = __ldg(reinterpret_cast<const float4*>(up) + lane);
    const float4 c = __ldg(reinterpret_cast<const float4*>(ip) + lane);

    // Linear terms on lane 0: independent chain, overlapped with the
    // gathers and the reduction, consumed only at the final store.
    float wsum = 0.0f;
    if (lane == 0)
        wsum = __ldg(&w[u]) + __ldg(&w[i]) + __ldg(&bptr[0]);

    float dot = a.x * c.x + a.y * c.y + a.z * c.z + a.w * c.w;

    // Reduce across the 16-lane group (contiguous within the warp).
    #pragma unroll
    for (int off = 8; off > 0; off >>= 1)
        dot += __shfl_xor_sync(0xffffffffu, dot, off);

    if (lane == 0)
        out[elem] = wsum + dot;
}

extern "C" void kernel_launch(void* const* d_in, const int* in_sizes, int n_in,
                              void* d_out, int out_size)
{
    const int*   inp = (const int*)d_in[0];    // INPUT int32 [BATCH,2]
    const float* w   = (const float*)d_in[1];  // w
    const float* b   = (const float*)d_in[2];  // b
    const float* V   = (const float*)d_in[3];  // V
    float*       out = (float*)d_out;          // [BATCH,1] float32

    const int threads = 256;
    const int blocks  = (BATCH * 16) / threads;   // 1024, exact
    fm_score_kernel<<<blocks, threads>>>(inp, w, b, V, out);
}